// round 6
// baseline (speedup 1.0000x reference)
#include <cuda_runtime.h>
#include <cuda_fp16.h>
#include <cstdint>

#define TT 8192
#define DD 2048
#define NCH 128
#define CL (TT/NCH)   // 64

// GEMM tiling (fp16 mma.sync m16n8k16), 4 warps, warp tile 64x64, NS=2, 3 CTA/SM
#define BM 128
#define BN 128
#define BKH 64                    // K halves per stage = 128B row
#define NKT (DD / BKH)            // 32
#define STAGE_B 32768             // A 16KB + B 16KB
#define SMEM_DYN (2 * STAGE_B)    // 65536

// ---------------- scratch (device globals; no allocations) ----------------
__device__ __half  g_xyh[(size_t)TT*DD];
__device__ __half  g_h0[(size_t)TT*DD];
__device__ __half  g_h1[(size_t)TT*DD];
__device__ __half  g_h2[(size_t)TT*DD];
__device__ __half  g_t0h[(size_t)TT*DD];
__device__ __half  g_wh[(size_t)7*DD*DD];
__device__ float g_k[(size_t)TT*DD];
__device__ float g_v[(size_t)TT*DD];
__device__ float g_r[(size_t)TT*DD];
__device__ float g_rz[(size_t)TT*DD];
__device__ float g_sa[NCH*DD], g_sb[NCH*DD], g_sp[NCH*DD];
__device__ float g_pa[NCH*DD], g_pb[NCH*DD], g_pp[NCH*DD];

// ---------------- helpers ----------------
__device__ __forceinline__ uint32_t saddr(const void* p) {
    return (uint32_t)__cvta_generic_to_shared(p);
}
__device__ __forceinline__ void cp_async16(uint32_t s, const void* g) {
    asm volatile("cp.async.cg.shared.global [%0], [%1], 16;" :: "r"(s), "l"(g));
}
__device__ __forceinline__ void cp_commit() {
    asm volatile("cp.async.commit_group;");
}
template <int N> __device__ __forceinline__ void cp_wait() {
    asm volatile("cp.async.wait_group %0;" :: "n"(N));
}
__device__ __forceinline__ void ldsm_x4(uint32_t r[4], uint32_t addr) {
    asm volatile("ldmatrix.sync.aligned.m8n8.x4.shared.b16 {%0,%1,%2,%3}, [%4];"
        : "=r"(r[0]), "=r"(r[1]), "=r"(r[2]), "=r"(r[3]) : "r"(addr));
}
__device__ __forceinline__ void mma16(float d[4], const uint32_t a[4],
                                      uint32_t b0, uint32_t b1) {
    asm volatile(
        "mma.sync.aligned.m16n8k16.row.col.f32.f16.f16.f32 "
        "{%0,%1,%2,%3}, {%4,%5,%6,%7}, {%8,%9}, {%0,%1,%2,%3};"
        : "+f"(d[0]), "+f"(d[1]), "+f"(d[2]), "+f"(d[3])
        : "r"(a[0]), "r"(a[1]), "r"(a[2]), "r"(a[3]), "r"(b0), "r"(b1));
}
#define SWZ(x) ((x) ^ (((x) >> 3) & 0x70))

// ---------------- elementwise kernels ----------------
__global__ __launch_bounds__(256) void wconv7_kernel(
    const float4* __restrict__ w0, const float4* __restrict__ w1,
    const float4* __restrict__ w2, const float4* __restrict__ w3,
    const float4* __restrict__ w4, const float4* __restrict__ w5,
    const float4* __restrict__ w6, __half2* __restrict__ out) {
    const int per = DD * DD / 4;
    int i = blockIdx.x * 256 + threadIdx.x;
    int w = i / per;
    int j = i - w * per;
    const float4* src;
    switch (w) {
        case 0: src = w0; break; case 1: src = w1; break;
        case 2: src = w2; break; case 3: src = w3; break;
        case 4: src = w4; break; case 5: src = w5; break;
        default: src = w6; break;
    }
    float4 v = src[j];
    __half2* o = out + (size_t)w * (DD * DD / 2) + (size_t)j * 2;
    o[0] = __floats2half2_rn(v.x, v.y);
    o[1] = __floats2half2_rn(v.z, v.w);
}

__global__ __launch_bounds__(256) void ln_kernel(const float* __restrict__ x,
                                                 const float* __restrict__ gw,
                                                 const float* __restrict__ gb,
                                                 __half* __restrict__ out) {
    int t = blockIdx.x;
    const float4* row = reinterpret_cast<const float4*>(x + (size_t)t * DD);
    float4 va[2];
    float s = 0.f, s2 = 0.f;
#pragma unroll
    for (int i = 0; i < 2; i++) {
        float4 v = row[threadIdx.x + i * 256];
        va[i] = v;
        s  += v.x + v.y + v.z + v.w;
        s2 += v.x*v.x + v.y*v.y + v.z*v.z + v.w*v.w;
    }
#pragma unroll
    for (int o = 16; o; o >>= 1) {
        s  += __shfl_xor_sync(0xffffffffu, s,  o);
        s2 += __shfl_xor_sync(0xffffffffu, s2, o);
    }
    __shared__ float ws[8], ws2[8];
    int wid = threadIdx.x >> 5, lane = threadIdx.x & 31;
    if (!lane) { ws[wid] = s; ws2[wid] = s2; }
    __syncthreads();
    float S = 0.f, S2 = 0.f;
#pragma unroll
    for (int i = 0; i < 8; i++) { S += ws[i]; S2 += ws2[i]; }
    float m = S * (1.0f / DD);
    float var = S2 * (1.0f / DD) - m * m;
    float inv = rsqrtf(var + 1e-5f);
    const float4* g4 = reinterpret_cast<const float4*>(gw);
    const float4* b4 = reinterpret_cast<const float4*>(gb);
    __half2* o2 = reinterpret_cast<__half2*>(out + (size_t)t * DD);
#pragma unroll
    for (int i = 0; i < 2; i++) {
        int c = threadIdx.x + i * 256;
        float4 v = va[i], g = g4[c], b = b4[c];
        float ox = (v.x - m) * inv * g.x + b.x;
        float oy = (v.y - m) * inv * g.y + b.y;
        float oz = (v.z - m) * inv * g.z + b.z;
        float ow = (v.w - m) * inv * g.w + b.w;
        o2[c * 2]     = __floats2half2_rn(ox, oy);
        o2[c * 2 + 1] = __floats2half2_rn(oz, ow);
    }
}

template <int N>
__global__ __launch_bounds__(256) void mixn_kernel(
    const __half2* __restrict__ xy,
    const float2* __restrict__ m0, const float2* __restrict__ m1,
    const float2* __restrict__ m2,
    __half2* __restrict__ o0, __half2* __restrict__ o1, __half2* __restrict__ o2) {
    int idx = blockIdx.x * 256 + threadIdx.x;
    const int DC = DD / 2;
    int t = idx / DC;
    int c = idx - t * DC;
    int tp = (t == 0) ? (TT - 1) : (t - 1);
    float2 a = __half22float2(xy[(size_t)tp * DC + c]);
    float2 b = __half22float2(xy[idx]);
    float2 mm;
    mm = m0[c];
    o0[idx] = __floats2half2_rn(a.x + mm.x * (b.x - a.x), a.y + mm.y * (b.y - a.y));
    mm = m1[c];
    o1[idx] = __floats2half2_rn(a.x + mm.x * (b.x - a.x), a.y + mm.y * (b.y - a.y));
    if (N == 3) {
        mm = m2[c];
        o2[idx] = __floats2half2_rn(a.x + mm.x * (b.x - a.x), a.y + mm.y * (b.y - a.y));
    }
}

// ---------------- WKV chunked scan ----------------
__global__ __launch_bounds__(256) void wkv_phase1(const float* __restrict__ k,
                                                  const float* __restrict__ v,
                                                  const float* __restrict__ td) {
    int c = blockIdx.x * 256 + threadIdx.x;
    int ch = blockIdx.y;
    float w = -__expf(td[c]);
    float aa = 0.f, bb = 0.f, pp = -1e38f;
    size_t base = (size_t)ch * CL * DD + c;
    for (int i = 0; i < CL; i++) {
        float kt = k[base + (size_t)i * DD];
        float vt = v[base + (size_t)i * DD];
        float ww2 = pp + w;
        float p2 = fmaxf(ww2, kt);
        float e1 = __expf(ww2 - p2), e2 = __expf(kt - p2);
        aa = e1 * aa + e2 * vt;
        bb = e1 * bb + e2;
        pp = p2;
    }
    int idx = ch * DD + c;
    g_sa[idx] = aa; g_sb[idx] = bb; g_sp[idx] = pp;
}

__global__ __launch_bounds__(256) void wkv_phase2(const float* __restrict__ td) {
    int c = blockIdx.x * 256 + threadIdx.x;
    float w = -__expf(td[c]);
    float clw = (float)CL * w;
    float aa = 0.f, bb = 0.f, pp = -1e38f;
    for (int ch = 0; ch < NCH; ch++) {
        int idx = ch * DD + c;
        g_pa[idx] = aa; g_pb[idx] = bb; g_pp[idx] = pp;
        float pd = pp + clw;
        float la = g_sa[idx], lb = g_sb[idx], lp = g_sp[idx];
        float p = fmaxf(pd, lp);
        float e1 = __expf(pd - p), e2 = __expf(lp - p);
        aa = e1 * aa + e2 * la;
        bb = e1 * bb + e2 * lb;
        pp = p;
    }
}

__global__ __launch_bounds__(256) void wkv_phase3(const float* __restrict__ k,
                                                  const float* __restrict__ v,
                                                  const float* __restrict__ r,
                                                  const float* __restrict__ tf,
                                                  const float* __restrict__ td,
                                                  __half* __restrict__ out) {
    int c = blockIdx.x * 256 + threadIdx.x;
    int ch = blockIdx.y;
    float w = -__expf(td[c]);
    float u = tf[c];
    int idx = ch * DD + c;
    float aa = g_pa[idx], bb = g_pb[idx], pp = g_pp[idx];
    size_t base = (size_t)ch * CL * DD + c;
    for (int i = 0; i < CL; i++) {
        size_t off = base + (size_t)i * DD;
        float kt = k[off], vt = v[off];
        float ww = u + kt;
        float p = fmaxf(pp, ww);
        float e1 = __expf(pp - p), e2 = __expf(ww - p);
        float o = (e1 * aa + e2 * vt) / (e1 * bb + e2);
        out[off] = __float2half_rn(o * r[off]);
        float ww2 = pp + w;
        float p2 = fmaxf(ww2, kt);
        e1 = __expf(ww2 - p2); e2 = __expf(kt - p2);
        aa = e1 * aa + e2 * vt;
        bb = e1 * bb + e2;
        pp = p2;
    }
}

// ---------------- fp16 mma.sync GEMM, z-batched jobs ----------------
// mode 0: plain  1: sigmoid  2: relu^2 (->half out)  3: +aux1  4: *aux1 + aux2
struct GJob {
    const __half* A; const __half* W; const float* bias;
    const float* aux1; const float* aux2; void* out; int mode;
};
struct GJobs { GJob j[3]; };

__global__ __launch_bounds__(128, 3) void gemm_h(GJobs jobs) {
    const GJob J = jobs.j[blockIdx.z];
    extern __shared__ __align__(1024) char smem[];
    const uint32_t sb = saddr(smem);
    const int tid = threadIdx.x;
    const int warp = tid >> 5, lane = tid & 31;
    const int bm = blockIdx.x * BM;
    const int bn = blockIdx.y * BN;
    const int wm = (warp >> 1) * 64;
    const int wn = (warp & 1) * 64;

    // hoisted producer addressing
    const uint32_t d0 = SWZ((uint32_t)((tid >> 3) * 128 + (tid & 7) * 16));
    const __half* gA = J.A + (size_t)bm * DD + (size_t)(tid >> 3) * DD + (tid & 7) * 8;
    const __half* gB = J.W + (size_t)bn * DD + (size_t)(tid >> 3) * DD + (tid & 7) * 8;

    float acc[4][8][4];
#pragma unroll
    for (int i = 0; i < 4; i++)
#pragma unroll
        for (int j = 0; j < 8; j++)
#pragma unroll
            for (int q = 0; q < 4; q++) acc[i][j][q] = 0.f;

    auto load_stage = [&](int kt) {
        const uint32_t st = sb + (kt & 1) * STAGE_B + d0;
        const int kk = kt * BKH;
#pragma unroll
        for (int i = 0; i < 8; i++) {
            const size_t so = (size_t)(i * 16) * DD + kk;
            cp_async16(st + i * 2048,         gA + so);
            cp_async16(st + 16384 + i * 2048, gB + so);
        }
    };

    load_stage(0); cp_commit();

    // hoisted consumer addressing
    const int lrow = lane & 15;
    const uint32_t kxor = (uint32_t)((lane & 7) << 4);
    const uint32_t khi  = (uint32_t)((lane >> 4) * 16);
    uint32_t arow_off[4], brow_off[4];
#pragma unroll
    for (int mi = 0; mi < 4; mi++) arow_off[mi] = (uint32_t)((wm + mi * 16 + lrow) * 128);
#pragma unroll
    for (int g = 0; g < 4; g++) brow_off[g] = (uint32_t)(16384 + (wn + g * 16 + lrow) * 128);

    for (int kt = 0; kt < NKT; kt++) {
        cp_wait<0>();
        __syncthreads();
        if (kt + 1 < NKT) load_stage(kt + 1);   // other buffer: consumed at kt-1
        cp_commit();

        const uint32_t st = sb + (kt & 1) * STAGE_B;
#pragma unroll
        for (int ks = 0; ks < 4; ks++) {
            const uint32_t kpart = ((uint32_t)(ks * 32) + khi) ^ kxor;
            uint32_t af[4][4], bf[4][4];
#pragma unroll
            for (int mi = 0; mi < 4; mi++) ldsm_x4(af[mi], st + arow_off[mi] + kpart);
#pragma unroll
            for (int g = 0; g < 4; g++)   ldsm_x4(bf[g],  st + brow_off[g] + kpart);
#pragma unroll
            for (int mi = 0; mi < 4; mi++)
#pragma unroll
                for (int g = 0; g < 4; g++) {
                    mma16(acc[mi][2 * g],     af[mi], bf[g][0], bf[g][2]);
                    mma16(acc[mi][2 * g + 1], af[mi], bf[g][1], bf[g][3]);
                }
        }
    }

    // ---------------- epilogue (runtime mode, uniform branch) ----------------
    const int mode = J.mode;
    const float* bias = J.bias;
#pragma unroll
    for (int mi = 0; mi < 4; mi++) {
        const int r0 = bm + wm + mi * 16 + (lane >> 2);
#pragma unroll
        for (int ni = 0; ni < 8; ni++) {
            const int c0 = bn + wn + ni * 8 + (lane & 3) * 2;
            const float b0 = bias[c0], b1 = bias[c0 + 1];
            const size_t i0 = (size_t)r0 * DD + c0;
            const size_t i1 = (size_t)(r0 + 8) * DD + c0;
            float v[4];
            v[0] = acc[mi][ni][0] + b0;
            v[1] = acc[mi][ni][1] + b1;
            v[2] = acc[mi][ni][2] + b0;
            v[3] = acc[mi][ni][3] + b1;
            if (mode == 1) {
#pragma unroll
                for (int q = 0; q < 4; q++) v[q] = 1.0f / (1.0f + expf(-v[q]));
            } else if (mode == 2) {
#pragma unroll
                for (int q = 0; q < 4; q++) { float t = v[q] > 0.f ? v[q] : 0.f; v[q] = t * t; }
            } else if (mode == 3) {
                v[0] += J.aux1[i0]; v[1] += J.aux1[i0 + 1];
                v[2] += J.aux1[i1]; v[3] += J.aux1[i1 + 1];
            } else if (mode == 4) {
                v[0] = v[0] * J.aux1[i0]     + J.aux2[i0];
                v[1] = v[1] * J.aux1[i0 + 1] + J.aux2[i0 + 1];
                v[2] = v[2] * J.aux1[i1]     + J.aux2[i1];
                v[3] = v[3] * J.aux1[i1 + 1] + J.aux2[i1 + 1];
            }
            if (mode == 2) {
                __half* oh = (__half*)J.out;
                *reinterpret_cast<__half2*>(oh + i0) = __floats2half2_rn(v[0], v[1]);
                *reinterpret_cast<__half2*>(oh + i1) = __floats2half2_rn(v[2], v[3]);
            } else {
                float* o = (float*)J.out;
                o[i0] = v[0]; o[i0 + 1] = v[1];
                o[i1] = v[2]; o[i1 + 1] = v[3];
            }
        }
    }
}

// ---------------- host orchestration ----------------
extern "C" void kernel_launch(void* const* d_in, const int* in_sizes, int n_in,
                              void* d_out, int out_size) {
    const float* x = (const float*)d_in[0];
    const float* w_src[7];
    const float* b_src[7];
    for (int i = 0; i < 7; i++) {
        w_src[i] = (const float*)d_in[1 + 2 * i];
        b_src[i] = (const float*)d_in[2 + 2 * i];
    }
    const float* ln1g = (const float*)d_in[15];
    const float* ln1b = (const float*)d_in[16];
    const float* ln2g = (const float*)d_in[17];
    const float* ln2b = (const float*)d_in[18];
    const float* mixk = (const float*)d_in[19];
    const float* mixv = (const float*)d_in[20];
    const float* mixr = (const float*)d_in[21];
    const float* fmk  = (const float*)d_in[22];
    const float* fmr  = (const float*)d_in[23];
    const float* tf   = (const float*)d_in[24];
    const float* td   = (const float*)d_in[25];
    float* out = (float*)d_out;

    __half *p_xyh, *p_h0, *p_h1, *p_h2, *p_t0h, *p_wh;
    float *p_k, *p_v, *p_r, *p_rz;
    cudaGetSymbolAddress((void**)&p_xyh, g_xyh);
    cudaGetSymbolAddress((void**)&p_h0,  g_h0);
    cudaGetSymbolAddress((void**)&p_h1,  g_h1);
    cudaGetSymbolAddress((void**)&p_h2,  g_h2);
    cudaGetSymbolAddress((void**)&p_t0h, g_t0h);
    cudaGetSymbolAddress((void**)&p_wh,  g_wh);
    cudaGetSymbolAddress((void**)&p_k,   g_k);
    cudaGetSymbolAddress((void**)&p_v,   g_v);
    cudaGetSymbolAddress((void**)&p_r,   g_r);
    cudaGetSymbolAddress((void**)&p_rz,  g_rz);

    cudaFuncSetAttribute(gemm_h, cudaFuncAttributeMaxDynamicSharedMemorySize, SMEM_DYN);

    const int nwc = 7 * (DD * DD / 4) / 256;
    wconv7_kernel<<<nwc, 256>>>((const float4*)w_src[0], (const float4*)w_src[1],
                                (const float4*)w_src[2], (const float4*)w_src[3],
                                (const float4*)w_src[4], (const float4*)w_src[5],
                                (const float4*)w_src[6], (__half2*)p_wh);

    const int nmix = TT * DD / 2 / 256;
    dim3 gwkv(DD / 256, NCH);
    const __half* W[7];
    for (int i = 0; i < 7; i++) W[i] = p_wh + (size_t)i * DD * DD;

    // --- attention branch ---
    ln_kernel<<<TT, 256>>>(x, ln1g, ln1b, p_xyh);
    mixn_kernel<3><<<nmix, 256>>>((const __half2*)p_xyh,
                                  (const float2*)mixk, (const float2*)mixv, (const float2*)mixr,
                                  (__half2*)p_h0, (__half2*)p_h1, (__half2*)p_h2);

    {   // fused k, v, r GEMMs
        GJobs js;
        js.j[0] = { p_h0, W[0], b_src[0], nullptr, nullptr, (void*)p_k, 0 };
        js.j[1] = { p_h1, W[1], b_src[1], nullptr, nullptr, (void*)p_v, 0 };
        js.j[2] = { p_h2, W[2], b_src[2], nullptr, nullptr, (void*)p_r, 1 };
        gemm_h<<<dim3(TT / BM, DD / BN, 3), 128, SMEM_DYN>>>(js);
    }

    wkv_phase1<<<gwkv, 256>>>(p_k, p_v, td);
    wkv_phase2<<<DD / 256, 256>>>(td);
    wkv_phase3<<<gwkv, 256>>>(p_k, p_v, p_r, tf, td, p_t0h);

    {   // atto GEMM + residual
        GJobs js{};
        js.j[0] = { p_t0h, W[3], b_src[3], x, nullptr, (void*)p_rz, 3 };
        gemm_h<<<dim3(TT / BM, DD / BN, 1), 128, SMEM_DYN>>>(js);
    }

    // --- FFN branch ---
    ln_kernel<<<TT, 256>>>(p_rz, ln2g, ln2b, p_xyh);
    mixn_kernel<2><<<nmix, 256>>>((const __half2*)p_xyh,
                                  (const float2*)fmr, (const float2*)fmk, nullptr,
                                  (__half2*)p_h0, (__half2*)p_h1, nullptr);

    {   // fused ffnr (sigmoid) + ffnk (relu^2 -> half)
        GJobs js{};
        js.j[0] = { p_h0, W[6], b_src[6], nullptr, nullptr, (void*)p_r,   1 };
        js.j[1] = { p_h1, W[4], b_src[4], nullptr, nullptr, (void*)p_t0h, 2 };
        gemm_h<<<dim3(TT / BM, DD / BN, 2), 128, SMEM_DYN>>>(js);
    }

    {   // ffnv GEMM + gating + residual
        GJobs js{};
        js.j[0] = { p_t0h, W[5], b_src[5], p_r, p_rz, (void*)out, 4 };
        gemm_h<<<dim3(TT / BM, DD / BN, 1), 128, SMEM_DYN>>>(js);
    }
}